// round 1
// baseline (speedup 1.0000x reference)
#include <cuda_runtime.h>
#include <cuda_bf16.h>

// x:    (b=8, t=50, f=129, c1=32, c2=32) float32  -> 52,838,400 elems
// mask: (g=8, f=129) float32                      -> 1,032 elems
// out:  (b=8, t=50, g=8, c1=32, c2=32) float32    -> 3,276,800 elems
//
// out[b,t,g,:,:] = sum_{f in band g} x[b,t,f,:,:] / count[g]
//
// HBM-bound: 211 MB read + 13 MB write. One CTA per (b,t) tile; 256 threads,
// one float4 (4 pixels) per thread; fully coalesced streaming loads.

#define N_F      129
#define N_BANDS  8
#define PIX4     256   // 32*32 pixels / 4 per float4

__global__ __launch_bounds__(256) void band_avg_kernel(
    const float* __restrict__ x,
    const float* __restrict__ masks,
    float* __restrict__ out)
{
    __shared__ int   f_list[N_BANDS][32];
    __shared__ int   cnt_sh[N_BANDS];
    __shared__ float inv_sh[N_BANDS];

    const int tid = threadIdx.x;

    // 8 threads build the per-band bin lists from the mask (generic, no
    // hardcoded band boundaries). Bands have at most 30 bins here; clamp 32.
    if (tid < N_BANDS) {
        int c = 0;
        float s = 0.0f;
        #pragma unroll 1
        for (int f = 0; f < N_F; ++f) {
            float m = masks[tid * N_F + f];
            s += m;
            if (m > 0.5f && c < 32) {
                f_list[tid][c++] = f;
            }
        }
        cnt_sh[tid] = c;
        inv_sh[tid] = 1.0f / s;   // count[g] = sum_f mask[g,f]
    }
    __syncthreads();

    const int bt = blockIdx.x;   // 0..399  (b*50 + t)

    // float4 views: per (b,t) tile, x has 129*256 float4; out has 8*256.
    const float4* __restrict__ xin =
        reinterpret_cast<const float4*>(x) + (size_t)bt * (N_F * PIX4) + tid;
    float4* __restrict__ o =
        reinterpret_cast<float4*>(out) + (size_t)bt * (N_BANDS * PIX4) + tid;

    #pragma unroll
    for (int g = 0; g < N_BANDS; ++g) {
        const int c = cnt_sh[g];
        float ax = 0.0f, ay = 0.0f, az = 0.0f, aw = 0.0f;
        #pragma unroll 4
        for (int k = 0; k < c; ++k) {
            const int f = f_list[g][k];
            float4 v = xin[(size_t)f * PIX4];
            ax += v.x; ay += v.y; az += v.z; aw += v.w;
        }
        const float inv = inv_sh[g];
        float4 r;
        r.x = ax * inv; r.y = ay * inv; r.z = az * inv; r.w = aw * inv;
        o[(size_t)g * PIX4] = r;
    }
}

extern "C" void kernel_launch(void* const* d_in, const int* in_sizes, int n_in,
                              void* d_out, int out_size)
{
    // Identify inputs by size (x = 52,838,400 elems; masks = 1,032 elems).
    const float* x     = (const float*)d_in[0];
    const float* masks = (const float*)d_in[1];
    if (n_in >= 2 && in_sizes[0] < in_sizes[1]) {
        x     = (const float*)d_in[1];
        masks = (const float*)d_in[0];
    }
    float* out = (float*)d_out;

    const int n_bt = 8 * 50;  // 400 (b,t) tiles
    band_avg_kernel<<<n_bt, 256>>>(x, masks, out);
}

// round 2
// speedup vs baseline: 1.4247x; 1.4247x over previous
#include <cuda_runtime.h>
#include <cuda_bf16.h>

// x:    (b=8, t=50, f=129, c1=32, c2=32) float32  -> 52,838,400 elems
// mask: (g=8, f=129) float32                      -> 1,032 elems
// out:  (b=8, t=50, g=8, c1=32, c2=32) float32    -> 3,276,800 elems
//
// out[b,t,g,:,:] = sum_{f in band g} x[b,t,f,:,:] / count[g]
//
// HBM-bound (211 MB read + 13 MB write, bands disjoint -> x read once).
// One CTA per (b,t,g): grid = 3200 -> 8 CTAs/SM resident (64 warps, full occ)
// so DRAM latency is hidden by warp parallelism. 256 threads, one float4 per
// thread; every LDG is a coalesced 16B streaming load.

#define N_F      129
#define N_BANDS  8
#define PIX4     256   // 32*32 pixels / 4 floats

__global__ __launch_bounds__(256) void band_avg_kernel(
    const float* __restrict__ x,
    const float* __restrict__ masks,
    float* __restrict__ out)
{
    __shared__ float m_sh[N_F];
    __shared__ int   f_list[32];
    __shared__ int   cnt_sh;
    __shared__ float inv_sh;

    const int tid = threadIdx.x;
    const int bid = blockIdx.x;
    const int g   = bid & (N_BANDS - 1);   // band index
    const int bt  = bid >> 3;              // (b,t) tile index, 0..399

    // Parallel-load this band's mask row into shared, then one thread builds
    // the bin list (generic: driven by mask contents, no hardcoded bands).
    if (tid < N_F) m_sh[tid] = masks[g * N_F + tid];
    __syncthreads();
    if (tid == 0) {
        int c = 0;
        float s = 0.0f;
        #pragma unroll 1
        for (int f = 0; f < N_F; ++f) {
            float m = m_sh[f];
            s += m;
            if (m > 0.5f && c < 32) f_list[c++] = f;
        }
        cnt_sh = c;
        inv_sh = 1.0f / s;
    }
    __syncthreads();

    const int   c   = cnt_sh;
    const float inv = inv_sh;

    const float4* __restrict__ xin =
        reinterpret_cast<const float4*>(x) + (size_t)bt * (N_F * PIX4) + tid;

    float ax = 0.0f, ay = 0.0f, az = 0.0f, aw = 0.0f;
    #pragma unroll 4
    for (int k = 0; k < c; ++k) {
        const int f = f_list[k];
        float4 v = __ldcs(&xin[(size_t)f * PIX4]);   // streaming: read-once data
        ax += v.x; ay += v.y; az += v.z; aw += v.w;
    }

    float4 r;
    r.x = ax * inv; r.y = ay * inv; r.z = az * inv; r.w = aw * inv;
    reinterpret_cast<float4*>(out)[(size_t)bid * PIX4 + tid] = r;
}

extern "C" void kernel_launch(void* const* d_in, const int* in_sizes, int n_in,
                              void* d_out, int out_size)
{
    // Identify inputs by size (x = 52,838,400 elems; masks = 1,032 elems).
    const float* x     = (const float*)d_in[0];
    const float* masks = (const float*)d_in[1];
    if (n_in >= 2 && in_sizes[0] < in_sizes[1]) {
        x     = (const float*)d_in[1];
        masks = (const float*)d_in[0];
    }
    float* out = (float*)d_out;

    const int n_blocks = 8 * 50 * N_BANDS;  // 3200 CTAs: one per (b,t,g)
    band_avg_kernel<<<n_blocks, 256>>>(x, masks, out);
}

// round 3
// speedup vs baseline: 1.7111x; 1.2010x over previous
#include <cuda_runtime.h>
#include <cuda_bf16.h>

// x:    (b=8, t=50, f=129, c1=32, c2=32) float32
// mask: (g=8, f=129) float32
// out:  (b=8, t=50, g=8, c1=32, c2=32) float32
//
// out[b,t,g,:,:] = sum_{f in band g} x[b,t,f,:,:] / count[g]
//
// HBM-bound streaming (211 MB read + 13 MB write). One CTA per (b,t,g),
// grid = 3200. Preamble is a parallel ballot-compaction (~200 cyc) instead of
// a serial scan; bands are contiguous f-ranges so the hot loop has pure
// arithmetic addressing -> 4 independent float4 LDGs in flight per thread.

#define N_F      129
#define N_BANDS  8
#define PIX4     256   // 32*32 pixels / 4 floats

__global__ __launch_bounds__(256, 6) void band_avg_kernel(
    const float* __restrict__ x,
    const float* __restrict__ masks,
    float* __restrict__ out)
{
    __shared__ unsigned warp_bits[8];
    __shared__ int   f_list[32];      // fallback only (non-contiguous mask)
    __shared__ int   info[3];         // start, cnt, contig
    __shared__ float inv_sh;

    const int tid = threadIdx.x;
    const int bid = blockIdx.x;
    const int g   = bid & (N_BANDS - 1);
    const int bt  = bid >> 3;

    // --- parallel mask compaction (threads 0..159 in warps 0..4) ---
    const int wid = tid >> 5;
    bool on = false;
    if (tid < N_F) on = (masks[g * N_F + tid] > 0.5f);
    if (wid < 5) {
        unsigned bal = __ballot_sync(0xffffffffu, on);
        if ((tid & 31) == 0) warp_bits[wid] = bal;
    }
    if (wid >= 5 && (tid & 31) == 0) warp_bits[wid] = 0u;
    __syncthreads();

    if (tid == 0) {
        int total = 0, first = -1, last = -1;
        #pragma unroll
        for (int w = 0; w < 5; ++w) {
            unsigned b = warp_bits[w];
            total += __popc(b);
            if (b) {
                if (first < 0) first = w * 32 + __ffs(b) - 1;
                last = w * 32 + 31 - __clz(b);
            }
        }
        info[0] = first;
        info[1] = total;
        info[2] = (last - first + 1 == total) ? 1 : 0;
        inv_sh  = 1.0f / (float)total;
    }
    // fallback list build (only consumed if non-contiguous)
    if (wid < 5 && on) {
        unsigned bal = __ballot_sync(__activemask(), true);
        // recompute per-warp bits locally to get prefix (bal over active only
        // is wrong; use warp_bits written above after sync below)
    }
    __syncthreads();

    const int   start  = info[0];
    const int   c      = info[1];
    const int   contig = info[2];
    const float inv    = inv_sh;

    if (!contig) {
        // rare/impossible path: build explicit list with ballot prefix
        if (tid < N_F && on) {
            int pos = 0;
            #pragma unroll
            for (int w = 0; w < 5; ++w) {
                unsigned b = warp_bits[w];
                if (w < wid) pos += __popc(b);
                else if (w == wid) pos += __popc(b & ((1u << (tid & 31)) - 1u));
            }
            if (pos < 32) f_list[pos] = tid;
        }
        __syncthreads();
    }

    const float4* __restrict__ xin =
        reinterpret_cast<const float4*>(x) + (size_t)bt * (N_F * PIX4) + tid;

    float ax = 0.0f, ay = 0.0f, az = 0.0f, aw = 0.0f;

    if (contig) {
        const float4* __restrict__ p = xin + (size_t)start * PIX4;
        #pragma unroll 4
        for (int k = 0; k < c; ++k) {
            float4 v = __ldcs(&p[(size_t)k * PIX4]);
            ax += v.x; ay += v.y; az += v.z; aw += v.w;
        }
    } else {
        #pragma unroll 2
        for (int k = 0; k < c; ++k) {
            float4 v = __ldcs(&xin[(size_t)f_list[k] * PIX4]);
            ax += v.x; ay += v.y; az += v.z; aw += v.w;
        }
    }

    float4 r;
    r.x = ax * inv; r.y = ay * inv; r.z = az * inv; r.w = aw * inv;
    reinterpret_cast<float4*>(out)[(size_t)bid * PIX4 + tid] = r;
}

extern "C" void kernel_launch(void* const* d_in, const int* in_sizes, int n_in,
                              void* d_out, int out_size)
{
    const float* x     = (const float*)d_in[0];
    const float* masks = (const float*)d_in[1];
    if (n_in >= 2 && in_sizes[0] < in_sizes[1]) {
        x     = (const float*)d_in[1];
        masks = (const float*)d_in[0];
    }
    float* out = (float*)d_out;

    const int n_blocks = 8 * 50 * N_BANDS;  // 3200 CTAs: one per (b,t,g)
    band_avg_kernel<<<n_blocks, 256>>>(x, masks, out);
}

// round 4
// speedup vs baseline: 1.7222x; 1.0065x over previous
#include <cuda_runtime.h>
#include <cuda_bf16.h>

// x:    (b=8, t=50, f=129, c1=32, c2=32) float32
// mask: (g=8, f=129) float32
// out:  (b=8, t=50, g=8, c1=32, c2=32) float32
//
// out[b,t,g,:,:] = sum_{f in band g} x[b,t,f,:,:] / count[g]
//
// HBM-bound streaming (211 MB read + 13 MB write). One CTA per (b,t, band-
// pair): bands g and 7-g are processed together — their bin counts pair to
// ~equal totals (32/34/30/32), so all 1600 CTAs do near-identical work and
// the ballot preamble is amortized over twice the DRAM traffic.

#define N_F      129
#define N_BANDS  8
#define PIX4     256   // 32*32 pixels / 4 floats

__global__ __launch_bounds__(256, 6) void band_avg_kernel(
    const float* __restrict__ x,
    const float* __restrict__ masks,
    float* __restrict__ out)
{
    __shared__ unsigned bits[2][5];        // ballot bitmap per band
    __shared__ int   s_start[2], s_cnt[2], s_contig[2];
    __shared__ float s_inv[2];

    const int tid = threadIdx.x;
    const int bid = blockIdx.x;            // 0..1599
    const int gp  = bid & 3;               // pair id 0..3
    const int bt  = bid >> 2;              // (b,t) tile 0..399
    const int g0  = gp;
    const int g1  = (N_BANDS - 1) - gp;

    // --- parallel mask compaction for both bands (warps 0..4) ---
    const int wid = tid >> 5;
    if (wid < 5) {
        bool on0 = false, on1 = false;
        if (tid < N_F) {
            on0 = (masks[g0 * N_F + tid] > 0.5f);
            on1 = (masks[g1 * N_F + tid] > 0.5f);
        }
        unsigned b0 = __ballot_sync(0xffffffffu, on0);
        unsigned b1 = __ballot_sync(0xffffffffu, on1);
        if ((tid & 31) == 0) { bits[0][wid] = b0; bits[1][wid] = b1; }
    }
    __syncthreads();

    if (tid < 2) {
        int total = 0, first = -1, last = -1;
        #pragma unroll
        for (int w = 0; w < 5; ++w) {
            unsigned b = bits[tid][w];
            total += __popc(b);
            if (b) {
                if (first < 0) first = w * 32 + __ffs(b) - 1;
                last = w * 32 + 31 - __clz(b);
            }
        }
        s_start[tid]  = first;
        s_cnt[tid]    = total;
        s_contig[tid] = (last - first + 1 == total) ? 1 : 0;
        s_inv[tid]    = 1.0f / (float)total;
    }
    __syncthreads();

    const float4* __restrict__ xin =
        reinterpret_cast<const float4*>(x) + (size_t)bt * (N_F * PIX4) + tid;
    float4* __restrict__ o4 =
        reinterpret_cast<float4*>(out) + (size_t)bt * (N_BANDS * PIX4) + tid;

    #pragma unroll 1
    for (int s = 0; s < 2; ++s) {
        const int   g     = s ? g1 : g0;
        const int   start = s_start[s];
        const int   c     = s_cnt[s];
        const float inv   = s_inv[s];

        float ax = 0.0f, ay = 0.0f, az = 0.0f, aw = 0.0f;

        if (s_contig[s]) {
            const float4* __restrict__ p = xin + (size_t)start * PIX4;
            #pragma unroll 4
            for (int k = 0; k < c; ++k) {
                float4 v = __ldcs(&p[(size_t)k * PIX4]);
                ax += v.x; ay += v.y; az += v.z; aw += v.w;
            }
        } else {
            // generic fallback: iterate the bitmap (unused for reference mask)
            #pragma unroll 1
            for (int f = 0; f < N_F; ++f) {
                if ((bits[s][f >> 5] >> (f & 31)) & 1u) {
                    float4 v = __ldcs(&xin[(size_t)f * PIX4]);
                    ax += v.x; ay += v.y; az += v.z; aw += v.w;
                }
            }
        }

        float4 r;
        r.x = ax * inv; r.y = ay * inv; r.z = az * inv; r.w = aw * inv;
        o4[(size_t)g * PIX4] = r;
    }
}

extern "C" void kernel_launch(void* const* d_in, const int* in_sizes, int n_in,
                              void* d_out, int out_size)
{
    const float* x     = (const float*)d_in[0];
    const float* masks = (const float*)d_in[1];
    if (n_in >= 2 && in_sizes[0] < in_sizes[1]) {
        x     = (const float*)d_in[1];
        masks = (const float*)d_in[0];
    }
    float* out = (float*)d_out;

    const int n_blocks = 8 * 50 * (N_BANDS / 2);  // 1600: one per (b,t,pair)
    band_avg_kernel<<<n_blocks, 256>>>(x, masks, out);
}